// round 16
// baseline (speedup 1.0000x reference)
#include <cuda_runtime.h>
#include <cuda_fp16.h>
#include <cstdint>

#define NN 50000
#define EE 800000
#define GG 1000
#define HH 128
#define LL 3
#define CC 6
#define EPS 1e-5f
#define NBLK 196                       // ceil(NN/256)

// ---------------- scratch (device globals; no allocation) ----------------
// g_degi / g_scancnt are zero on entry each execution: module-load zero-init
// covers run #1; k_mlp's tail re-zeroes them for the next run.
__device__ int   g_degi[NN];
__device__ int   g_blocksum[NBLK];
__device__ int   g_scancnt;
__device__ int   g_rowptr[NN + 1];
__device__ int   g_cursor[NN];
__device__ int   g_csrsrc[EE];
__device__ float g_dis[NN];
__device__ __half2 g_hsb[NN * 64];   // h * dis[row], fp16 packed
__device__ float g_agg[NN * HH];     // aggregated + self + bias (fp32)
__device__ float g_sum[HH];
__device__ float g_sumsq[HH];
__device__ float g_pool[GG * HH];
__device__ float g_cnt[GG];

// ---------------- degree / CSR build ----------------
__global__ void k_deg_count(const int* __restrict__ dst) {
    int e4 = blockIdx.x * blockDim.x + threadIdx.x;
    if (e4 < EE / 4) {
        int4 d = ((const int4*)dst)[e4];
        atomicAdd(&g_degi[d.x], 1);
        atomicAdd(&g_degi[d.y], 1);
        atomicAdd(&g_degi[d.z], 1);
        atomicAdd(&g_degi[d.w], 1);
    }
}

__global__ void k_csr_mid() {
    __shared__ int sh[256];
    __shared__ int shb[256];
    int t = threadIdx.x;
    int b = blockIdx.x;
    int n = b * 256 + t;

    int deg = (n < NN) ? g_degi[n] : 0;
    if (n < NN) g_dis[n] = rsqrtf((float)deg + 1.0f);

    sh[t] = deg;
    __syncthreads();
#pragma unroll
    for (int off = 1; off < 256; off <<= 1) {
        int u = (t >= off) ? sh[t - off] : 0;
        __syncthreads();
        sh[t] += u;
        __syncthreads();
    }
    if (t == 255) g_blocksum[b] = sh[255];
    __syncthreads();
    if (t == 0) {
        __threadfence();
        atomicAdd(&g_scancnt, 1);
        while (*(volatile int*)&g_scancnt < NBLK) { }
        __threadfence();
    }
    __syncthreads();

    int v = (t < NBLK) ? g_blocksum[t] : 0;
    shb[t] = v;
    __syncthreads();
#pragma unroll
    for (int off = 1; off < 256; off <<= 1) {
        int u = (t >= off) ? shb[t - off] : 0;
        __syncthreads();
        shb[t] += u;
        __syncthreads();
    }
    int blockoff = (b > 0) ? shb[b - 1] : 0;

    if (n < NN) {
        int excl = blockoff + sh[t] - deg;
        g_rowptr[n] = excl;
        g_cursor[n] = excl;
    }
    if (b == 0 && t == 0) g_rowptr[NN] = EE;
}

__global__ void k_fill(const int* __restrict__ src, const int* __restrict__ dst) {
    int e4 = blockIdx.x * blockDim.x + threadIdx.x;
    if (e4 < EE / 4) {
        int4 d = ((const int4*)dst)[e4];
        int4 s = ((const int4*)src)[e4];
        int p0 = atomicAdd(&g_cursor[d.x], 1);
        int p1 = atomicAdd(&g_cursor[d.y], 1);
        int p2 = atomicAdd(&g_cursor[d.z], 1);
        int p3 = atomicAdd(&g_cursor[d.w], 1);
        g_csrsrc[p0] = s.x;
        g_csrsrc[p1] = s.y;
        g_csrsrc[p2] = s.z;
        g_csrsrc[p3] = s.w;
    }
}

// ---------------- fp16 MMA helpers ----------------
#define MMA_F16(C, A, B0, B1)                                                  \
    asm volatile("mma.sync.aligned.m16n8k16.row.col.f32.f16.f16.f32 "         \
                 "{%0,%1,%2,%3}, {%4,%5,%6,%7}, {%8,%9}, {%0,%1,%2,%3};"      \
                 : "+f"((C)[0]), "+f"((C)[1]), "+f"((C)[2]), "+f"((C)[3])     \
                 : "r"((A)[0]), "r"((A)[1]), "r"((A)[2]), "r"((A)[3]),        \
                   "r"(B0), "r"(B1))

__device__ __forceinline__ uint32_t smem_u32(const void* p) {
    return (uint32_t)__cvta_generic_to_shared(p);
}

// ---------------- GEMM: g_hsb = fp16( BN?(A)[N,128] @ B[128,128] * dis[row] )
// fp16 tensor MMA, double-buffered smem, register-prefetch pipeline.
// One __syncthreads per k-chunk. FIX vs R15: explicit barrier after the
// s_scale/s_shift init — the prologue store_stage reads them pre-loop.
#define APH 24    // A smem row stride (halves)
#define BPH 136   // B smem row stride (halves)
__global__ void __launch_bounds__(256, 2) k_gemm(const float* __restrict__ Ain,
                                                 const float* __restrict__ B,
                                                 const float* __restrict__ gamma,
                                                 const float* __restrict__ beta,
                                                 int apply_bn) {
    const float* __restrict__ A = Ain ? Ain : g_agg;
    __shared__ __half Ah[2][128][APH];
    __shared__ __half Bh[2][16][BPH];
    __shared__ __align__(16) float s_scale[128];
    __shared__ __align__(16) float s_shift[128];

    int row0 = blockIdx.x * 128;
    int t = threadIdx.x;
    if (apply_bn && t < 128) {
        const float invN = 1.0f / (float)NN;
        float mu = g_sum[t] * invN;
        float var = g_sumsq[t] * invN - mu * mu;
        float sc = gamma[t] * rsqrtf(var + EPS);
        s_scale[t] = sc;
        s_shift[t] = beta[t] - mu * sc;
    }
    __syncthreads();   // REQUIRED: prologue store_stage below reads s_scale/s_shift

    int w = t >> 5, lane = t & 31;
    int wr = w & 3, wc = w >> 2;
    int g = lane >> 2, tig = lane & 3;

    int g4 = lane >> 3, li = lane & 7;
    int arow_off = (g4 & 1) * 8 + li;
    int akoff = (g4 >> 1) * 8;
    int blrow = lane & 15;

    // staging indices (fixed per thread)
    const int ar = t >> 1;              // A: 2 float4 per row -> row = t/2
    const int akq = (t & 1) * 2;        // A: k-quad pair 0/2 (each f4 = 4 k)
    const int bkr = t >> 4;             // B: 16 rows x 16 f4 -> row = t/16
    const int bcq = (t & 15) * 2;       // B: col-quad pair

    float4 af0, af1, bf0, bf1;

    auto load_regs = [&](int k0) {
        int grow = row0 + ar;
        if (grow < NN) {
            af0 = *(const float4*)&A[grow * 128 + k0 + akq * 4];
            af1 = *(const float4*)&A[grow * 128 + k0 + akq * 4 + 4];
        } else {
            af0 = make_float4(0.f, 0.f, 0.f, 0.f);
            af1 = af0;
        }
        bf0 = *(const float4*)&B[(k0 + bkr) * 128 + bcq * 4];
        bf1 = *(const float4*)&B[(k0 + bkr) * 128 + bcq * 4 + 4];
    };

    auto store_stage = [&](int k0, int buf) {
        float4 v0 = af0, v1 = af1;
        if (apply_bn) {
            float4 sc0 = ((const float4*)s_scale)[(k0 >> 2) + akq];
            float4 sh0 = ((const float4*)s_shift)[(k0 >> 2) + akq];
            float4 sc1 = ((const float4*)s_scale)[(k0 >> 2) + akq + 1];
            float4 sh1 = ((const float4*)s_shift)[(k0 >> 2) + akq + 1];
            v0.x = fmaxf(v0.x * sc0.x + sh0.x, 0.f);
            v0.y = fmaxf(v0.y * sc0.y + sh0.y, 0.f);
            v0.z = fmaxf(v0.z * sc0.z + sh0.z, 0.f);
            v0.w = fmaxf(v0.w * sc0.w + sh0.w, 0.f);
            v1.x = fmaxf(v1.x * sc1.x + sh1.x, 0.f);
            v1.y = fmaxf(v1.y * sc1.y + sh1.y, 0.f);
            v1.z = fmaxf(v1.z * sc1.z + sh1.z, 0.f);
            v1.w = fmaxf(v1.w * sc1.w + sh1.w, 0.f);
        }
        *(__half2*)&Ah[buf][ar][akq * 4]     = __floats2half2_rn(v0.x, v0.y);
        *(__half2*)&Ah[buf][ar][akq * 4 + 2] = __floats2half2_rn(v0.z, v0.w);
        *(__half2*)&Ah[buf][ar][akq * 4 + 4] = __floats2half2_rn(v1.x, v1.y);
        *(__half2*)&Ah[buf][ar][akq * 4 + 6] = __floats2half2_rn(v1.z, v1.w);
        *(__half2*)&Bh[buf][bkr][bcq * 4]     = __floats2half2_rn(bf0.x, bf0.y);
        *(__half2*)&Bh[buf][bkr][bcq * 4 + 2] = __floats2half2_rn(bf0.z, bf0.w);
        *(__half2*)&Bh[buf][bkr][bcq * 4 + 4] = __floats2half2_rn(bf1.x, bf1.y);
        *(__half2*)&Bh[buf][bkr][bcq * 4 + 6] = __floats2half2_rn(bf1.z, bf1.w);
    };

    float c[2][8][4];
#pragma unroll
    for (int mt = 0; mt < 2; mt++)
#pragma unroll
        for (int nt = 0; nt < 8; nt++)
#pragma unroll
            for (int i = 0; i < 4; i++) c[mt][nt][i] = 0.0f;

    // prologue: chunk 0 into buf 0
    load_regs(0);
    store_stage(0, 0);

#pragma unroll
    for (int i = 0; i < 8; i++) {
        __syncthreads();    // buf[i&1] ready; buf[(i+1)&1] free (readers synced)
        if (i < 7) load_regs((i + 1) * 16);

        int buf = i & 1;
        uint32_t afr[2][4];
#pragma unroll
        for (int mt = 0; mt < 2; mt++) {
            uint32_t aaddr = smem_u32(&Ah[buf][wr * 32 + mt * 16 + arow_off][akoff]);
            asm volatile("ldmatrix.sync.aligned.m8n8.x4.shared.b16 "
                         "{%0,%1,%2,%3}, [%4];"
                         : "=r"(afr[mt][0]), "=r"(afr[mt][1]),
                           "=r"(afr[mt][2]), "=r"(afr[mt][3])
                         : "r"(aaddr));
        }
#pragma unroll
        for (int nt = 0; nt < 8; nt++) {
            int colbase = wc * 64 + nt * 8;
            uint32_t baddr = smem_u32(&Bh[buf][blrow][colbase]);
            uint32_t b0, b1;
            asm volatile("ldmatrix.sync.aligned.m8n8.x2.trans.shared.b16 "
                         "{%0,%1}, [%2];"
                         : "=r"(b0), "=r"(b1)
                         : "r"(baddr));
#pragma unroll
            for (int mt = 0; mt < 2; mt++)
                MMA_F16(c[mt][nt], afr[mt], b0, b1);
        }

        if (i < 7) store_stage((i + 1) * 16, (i + 1) & 1);
    }

    // epilogue: scale by dis[row], convert to fp16x2, write g_hsb
#pragma unroll
    for (int mt = 0; mt < 2; mt++) {
        int r0 = row0 + wr * 32 + mt * 16 + g;
        int r1 = r0 + 8;
        float d0 = (r0 < NN) ? g_dis[r0] : 0.0f;
        float d1 = (r1 < NN) ? g_dis[r1] : 0.0f;
#pragma unroll
        for (int nt = 0; nt < 8; nt++) {
            int colh = wc * 32 + nt * 4 + tig;
            if (r0 < NN)
                g_hsb[r0 * 64 + colh] = __floats2half2_rn(c[mt][nt][0] * d0,
                                                          c[mt][nt][1] * d0);
            if (r1 < NN)
                g_hsb[r1 * 64 + colh] = __floats2half2_rn(c[mt][nt][2] * d1,
                                                          c[mt][nt][3] * d1);
        }
    }
}

// ---------------- CSR pull aggregation: warp per node ----------------------
__global__ void k_aggregate(const float* __restrict__ bias) {
    int t = blockIdx.x * blockDim.x + threadIdx.x;
    if (blockIdx.x == 0 && threadIdx.x < 128) {
        g_sum[threadIdx.x] = 0.0f;
        g_sumsq[threadIdx.x] = 0.0f;
    }
    int n = t >> 5, q = t & 31;
    if (n >= NN) return;
    int beg = g_rowptr[n], end = g_rowptr[n + 1];

    uint2 u = *(const uint2*)(g_hsb + n * 64 + q * 2);   // self term
    float2 p0 = __half22float2(*reinterpret_cast<__half2*>(&u.x));
    float2 p1 = __half22float2(*reinterpret_cast<__half2*>(&u.y));
    float a0 = p0.x, a1 = p0.y, a2 = p1.x, a3 = p1.y;

    for (int i = beg; i < end; i++) {
        int s = g_csrsrc[i];                              // warp-uniform broadcast
        uint2 v = *(const uint2*)(g_hsb + s * 64 + q * 2);
        float2 q0 = __half22float2(*reinterpret_cast<__half2*>(&v.x));
        float2 q1 = __half22float2(*reinterpret_cast<__half2*>(&v.y));
        a0 += q0.x; a1 += q0.y; a2 += q1.x; a3 += q1.y;
    }
    float d = g_dis[n];
    float4 b = ((const float4*)bias)[q];
    float4 acc;
    acc.x = a0 * d + b.x;
    acc.y = a1 * d + b.y;
    acc.z = a2 * d + b.z;
    acc.w = a3 * d + b.w;
    ((float4*)g_agg)[n * 32 + q] = acc;
}

// ---------------- BN stats (streaming); also zeroes pool buffers ----------
__global__ void k_bnstats() {
    int c = threadIdx.x;
    int zt = blockIdx.x * blockDim.x + c;
    if (zt < GG * HH) g_pool[zt] = 0.0f;
    if (zt < GG) g_cnt[zt] = 0.0f;

    float s = 0.0f, ss = 0.0f;
    for (int n = blockIdx.x; n < NN; n += gridDim.x) {
        float v = g_agg[n * HH + c];
        s += v;
        ss += v * v;
    }
    atomicAdd(&g_sum[c], s);
    atomicAdd(&g_sumsq[c], ss);
}

// ---------------- pooling (BN apply + relu from raw stats) ----------------
__global__ void k_pool(const int* __restrict__ batch,
                       const float* __restrict__ gamma,
                       const float* __restrict__ beta) {
    int t = blockIdx.x * blockDim.x + threadIdx.x;
    int n = t >> 5, q = t & 31;
    if (n >= NN) return;
    int g = batch[n];
    const float invN = 1.0f / (float)NN;
    float4 v = ((const float4*)g_agg)[n * 32 + q];
    float4 sm = ((const float4*)g_sum)[q];
    float4 sq = ((const float4*)g_sumsq)[q];
    float4 ga = ((const float4*)gamma)[q];
    float4 be = ((const float4*)beta)[q];
    float4 o;
    {
        float mu = sm.x * invN; float var = sq.x * invN - mu * mu;
        float sc = ga.x * rsqrtf(var + EPS);
        o.x = fmaxf(v.x * sc + (be.x - mu * sc), 0.f);
    }
    {
        float mu = sm.y * invN; float var = sq.y * invN - mu * mu;
        float sc = ga.y * rsqrtf(var + EPS);
        o.y = fmaxf(v.y * sc + (be.y - mu * sc), 0.f);
    }
    {
        float mu = sm.z * invN; float var = sq.z * invN - mu * mu;
        float sc = ga.z * rsqrtf(var + EPS);
        o.z = fmaxf(v.z * sc + (be.z - mu * sc), 0.f);
    }
    {
        float mu = sm.w * invN; float var = sq.w * invN - mu * mu;
        float sc = ga.w * rsqrtf(var + EPS);
        o.w = fmaxf(v.w * sc + (be.w - mu * sc), 0.f);
    }
    float* out = g_pool + (size_t)g * HH + q * 4;
    asm volatile("red.global.add.v4.f32 [%0], {%1,%2,%3,%4};"
                 :: "l"(out), "f"(o.x), "f"(o.y), "f"(o.z), "f"(o.w)
                 : "memory");
    if (q == 0) atomicAdd(&g_cnt[g], 1.0f);
}

// ---------------- MLP head (+ re-arm g_degi / g_scancnt) ------------------
__global__ void k_mlp(const float* __restrict__ w1, const float* __restrict__ b1,
                      const float* __restrict__ w2, const float* __restrict__ b2,
                      float* __restrict__ out) {
    int g = blockIdx.x;
    int t = threadIdx.x;       // 128

    int zi = g * 128 + t;
    if (zi < NN) g_degi[zi] = 0;
    if (zi == 0) g_scancnt = 0;

    __shared__ float p[128];
    __shared__ float red[4][8];
    float inv = 1.0f / fmaxf(g_cnt[g], 1.0f);
    p[t] = g_pool[g * HH + t] * inv;
    __syncthreads();
    float acc = b1[t];
#pragma unroll 8
    for (int k = 0; k < 128; k++) acc += p[k] * w1[k * 128 + t];
    float h = fmaxf(acc, 0.0f);
    float pr[CC];
#pragma unroll
    for (int c = 0; c < CC; c++) pr[c] = h * w2[t * CC + c];
#pragma unroll
    for (int off = 16; off > 0; off >>= 1)
#pragma unroll
        for (int c = 0; c < CC; c++) pr[c] += __shfl_down_sync(0xffffffffu, pr[c], off);
    int w = t >> 5, lane = t & 31;
    if (lane == 0)
#pragma unroll
        for (int c = 0; c < CC; c++) red[w][c] = pr[c];
    __syncthreads();
    if (t < CC) {
        out[g * CC + t] = red[0][t] + red[1][t] + red[2][t] + red[3][t] + b2[t];
    }
}

// ---------------- launch ----------------
extern "C" void kernel_launch(void* const* d_in, const int* in_sizes, int n_in,
                              void* d_out, int out_size) {
    const float* x      = (const float*)d_in[0];
    const int*   ei     = (const int*)d_in[1];
    const int*   batch  = (const int*)d_in[2];
    const float* conv_w = (const float*)d_in[3];
    const float* conv_b = (const float*)d_in[4];
    const float* bn_g   = (const float*)d_in[5];
    const float* bn_b   = (const float*)d_in[6];
    const float* w1     = (const float*)d_in[7];
    const float* b1     = (const float*)d_in[8];
    const float* w2     = (const float*)d_in[9];
    const float* b2     = (const float*)d_in[10];
    float* out = (float*)d_out;

    const int* src = ei;
    const int* dst = ei + EE;

    k_deg_count<<<(EE / 4 + 255) / 256, 256>>>(dst);
    k_csr_mid<<<NBLK, 256>>>();
    k_fill<<<(EE / 4 + 255) / 256, 256>>>(src, dst);

    const int ggrid = (NN + 127) / 128;    // 391
    const int nwarp_blocks = (int)(((long long)NN * 32 + 255) / 256);

    for (int l = 0; l < LL; l++) {
        const float* A = (l == 0) ? x : nullptr;   // nullptr -> g_agg with BN prologue
        const float* ga = (l > 0) ? bn_g + (size_t)(l - 1) * HH : nullptr;
        const float* be = (l > 0) ? bn_b + (size_t)(l - 1) * HH : nullptr;
        k_gemm<<<ggrid, 256>>>(A, conv_w + (size_t)l * HH * HH, ga, be, l > 0 ? 1 : 0);
        k_aggregate<<<nwarp_blocks, 256>>>(conv_b + (size_t)l * HH);
        k_bnstats<<<1024, 128>>>();
    }

    k_pool<<<nwarp_blocks, 256>>>(batch, bn_g + (size_t)(LL - 1) * HH,
                                  bn_b + (size_t)(LL - 1) * HH);
    k_mlp<<<GG, 128>>>(w1, b1, w2, b2, out);
}

// round 17
// speedup vs baseline: 1.3808x; 1.3808x over previous
#include <cuda_runtime.h>
#include <cuda_fp16.h>
#include <cstdint>

#define NN 50000
#define EE 800000
#define GG 1000
#define HH 128
#define LL 3
#define CC 6
#define EPS 1e-5f
#define NBLK 196                       // ceil(NN/256)

// ---------------- scratch (device globals; no allocation) ----------------
// g_degi / g_scancnt are zero on entry each execution: module-load zero-init
// covers run #1; k_mlp's tail re-zeroes them for the next run.
__device__ int   g_degi[NN];
__device__ int   g_blocksum[NBLK];
__device__ int   g_scancnt;
__device__ int   g_rowptr[NN + 1];
__device__ int   g_cursor[NN];
__device__ int   g_csrsrc[EE];
__device__ float g_dis[NN];
__device__ __half2 g_hsb[NN * 64];   // h * dis[row], fp16 packed
__device__ float g_agg[NN * HH];     // aggregated + self + bias (fp32)
__device__ float g_sum[HH];
__device__ float g_sumsq[HH];
__device__ float g_pool[GG * HH];
__device__ float g_cnt[GG];

// ---------------- degree / CSR build ----------------
__global__ void k_deg_count(const int* __restrict__ dst) {
    int e4 = blockIdx.x * blockDim.x + threadIdx.x;
    if (e4 < EE / 4) {
        int4 d = ((const int4*)dst)[e4];
        atomicAdd(&g_degi[d.x], 1);
        atomicAdd(&g_degi[d.y], 1);
        atomicAdd(&g_degi[d.z], 1);
        atomicAdd(&g_degi[d.w], 1);
    }
}

__global__ void k_csr_mid() {
    __shared__ int sh[256];
    __shared__ int shb[256];
    int t = threadIdx.x;
    int b = blockIdx.x;
    int n = b * 256 + t;

    int deg = (n < NN) ? g_degi[n] : 0;
    if (n < NN) g_dis[n] = rsqrtf((float)deg + 1.0f);

    sh[t] = deg;
    __syncthreads();
#pragma unroll
    for (int off = 1; off < 256; off <<= 1) {
        int u = (t >= off) ? sh[t - off] : 0;
        __syncthreads();
        sh[t] += u;
        __syncthreads();
    }
    if (t == 255) g_blocksum[b] = sh[255];
    __syncthreads();
    if (t == 0) {
        __threadfence();
        atomicAdd(&g_scancnt, 1);
        while (*(volatile int*)&g_scancnt < NBLK) { }
        __threadfence();
    }
    __syncthreads();

    int v = (t < NBLK) ? g_blocksum[t] : 0;
    shb[t] = v;
    __syncthreads();
#pragma unroll
    for (int off = 1; off < 256; off <<= 1) {
        int u = (t >= off) ? shb[t - off] : 0;
        __syncthreads();
        shb[t] += u;
        __syncthreads();
    }
    int blockoff = (b > 0) ? shb[b - 1] : 0;

    if (n < NN) {
        int excl = blockoff + sh[t] - deg;
        g_rowptr[n] = excl;
        g_cursor[n] = excl;
    }
    if (b == 0 && t == 0) g_rowptr[NN] = EE;
}

__global__ void k_fill(const int* __restrict__ src, const int* __restrict__ dst) {
    int e4 = blockIdx.x * blockDim.x + threadIdx.x;
    if (e4 < EE / 4) {
        int4 d = ((const int4*)dst)[e4];
        int4 s = ((const int4*)src)[e4];
        int p0 = atomicAdd(&g_cursor[d.x], 1);
        int p1 = atomicAdd(&g_cursor[d.y], 1);
        int p2 = atomicAdd(&g_cursor[d.z], 1);
        int p3 = atomicAdd(&g_cursor[d.w], 1);
        g_csrsrc[p0] = s.x;
        g_csrsrc[p1] = s.y;
        g_csrsrc[p2] = s.z;
        g_csrsrc[p3] = s.w;
    }
}

// ---------------- fp16 MMA helpers ----------------
#define MMA_F16(C, A, B0, B1)                                                  \
    asm volatile("mma.sync.aligned.m16n8k16.row.col.f32.f16.f16.f32 "         \
                 "{%0,%1,%2,%3}, {%4,%5,%6,%7}, {%8,%9}, {%0,%1,%2,%3};"      \
                 : "+f"((C)[0]), "+f"((C)[1]), "+f"((C)[2]), "+f"((C)[3])     \
                 : "r"((A)[0]), "r"((A)[1]), "r"((A)[2]), "r"((A)[3]),        \
                   "r"(B0), "r"(B1))

__device__ __forceinline__ uint32_t smem_u32(const void* p) {
    return (uint32_t)__cvta_generic_to_shared(p);
}

// ---------------- GEMM: g_hsb = fp16( BN?(A)[N,128] @ B[128,128] * dis[row] )
// fp16 tensor MMA, 64x128 block tile (8 warps, 2x4; warp tile 32x32).
// Halved accumulators vs the 128-tile version -> ~3 CTAs/SM for latency hiding.
#define APH 24    // A smem row stride (halves)
#define BPH 136   // B smem row stride (halves)
__global__ void __launch_bounds__(256) k_gemm(const float* __restrict__ Ain,
                                              const float* __restrict__ B,
                                              const float* __restrict__ gamma,
                                              const float* __restrict__ beta,
                                              int apply_bn) {
    const float* __restrict__ A = Ain ? Ain : g_agg;
    __shared__ __half Ah[64][APH];
    __shared__ __half Bh[16][BPH];
    __shared__ __align__(16) float s_scale[128];
    __shared__ __align__(16) float s_shift[128];

    int row0 = blockIdx.x * 64;
    int t = threadIdx.x;
    if (apply_bn && t < 128) {
        const float invN = 1.0f / (float)NN;
        float mu = g_sum[t] * invN;
        float var = g_sumsq[t] * invN - mu * mu;
        float sc = gamma[t] * rsqrtf(var + EPS);
        s_scale[t] = sc;
        s_shift[t] = beta[t] - mu * sc;
    }
    __syncthreads();

    int w = t >> 5, lane = t & 31;
    int wr = w & 1, wc = w >> 1;        // 2 row groups x 4 col groups
    int g = lane >> 2, tig = lane & 3;

    int g4 = lane >> 3, li = lane & 7;
    int arow_off = (g4 & 1) * 8 + li;
    int akoff = (g4 >> 1) * 8;
    int blrow = lane & 15;

    float c[2][4][4];
#pragma unroll
    for (int mt = 0; mt < 2; mt++)
#pragma unroll
        for (int nt = 0; nt < 4; nt++)
#pragma unroll
            for (int i = 0; i < 4; i++) c[mt][nt][i] = 0.0f;

    for (int k0 = 0; k0 < 128; k0 += 16) {
        // ---- stage A chunk: 64 rows x 16 k (256 float4, 1 per thread) ----
        {
            int r = t >> 2;              // 4 float4 per row
            int kq = t & 3;
            int grow = row0 + r;
            float4 v = make_float4(0.f, 0.f, 0.f, 0.f);
            if (grow < NN) v = *(const float4*)&A[grow * 128 + k0 + kq * 4];
            if (apply_bn) {
                float4 sc = ((const float4*)s_scale)[(k0 >> 2) + kq];
                float4 sh = ((const float4*)s_shift)[(k0 >> 2) + kq];
                v.x = fmaxf(v.x * sc.x + sh.x, 0.f);
                v.y = fmaxf(v.y * sc.y + sh.y, 0.f);
                v.z = fmaxf(v.z * sc.z + sh.z, 0.f);
                v.w = fmaxf(v.w * sc.w + sh.w, 0.f);
            }
            *(__half2*)&Ah[r][kq * 4]     = __floats2half2_rn(v.x, v.y);
            *(__half2*)&Ah[r][kq * 4 + 2] = __floats2half2_rn(v.z, v.w);
        }
        // ---- stage B chunk: 16 k x 128 cols (512 float4, 2 per thread) ----
#pragma unroll
        for (int i = 0; i < 2; i++) {
            int fi = t + i * 256;
            int kr = fi >> 5;            // 32 float4 per row
            int cq = fi & 31;
            float4 v = *(const float4*)&B[(k0 + kr) * 128 + cq * 4];
            *(__half2*)&Bh[kr][cq * 4]     = __floats2half2_rn(v.x, v.y);
            *(__half2*)&Bh[kr][cq * 4 + 2] = __floats2half2_rn(v.z, v.w);
        }
        __syncthreads();

        uint32_t afr[2][4];
#pragma unroll
        for (int mt = 0; mt < 2; mt++) {
            uint32_t aaddr = smem_u32(&Ah[wr * 32 + mt * 16 + arow_off][akoff]);
            asm volatile("ldmatrix.sync.aligned.m8n8.x4.shared.b16 "
                         "{%0,%1,%2,%3}, [%4];"
                         : "=r"(afr[mt][0]), "=r"(afr[mt][1]),
                           "=r"(afr[mt][2]), "=r"(afr[mt][3])
                         : "r"(aaddr));
        }
#pragma unroll
        for (int nt = 0; nt < 4; nt++) {
            int colbase = wc * 32 + nt * 8;
            uint32_t baddr = smem_u32(&Bh[blrow][colbase]);
            uint32_t b0, b1;
            asm volatile("ldmatrix.sync.aligned.m8n8.x2.trans.shared.b16 "
                         "{%0,%1}, [%2];"
                         : "=r"(b0), "=r"(b1)
                         : "r"(baddr));
#pragma unroll
            for (int mt = 0; mt < 2; mt++)
                MMA_F16(c[mt][nt], afr[mt], b0, b1);
        }
        __syncthreads();
    }

    // epilogue: scale by dis[row], convert to fp16x2, write g_hsb
#pragma unroll
    for (int mt = 0; mt < 2; mt++) {
        int r0 = row0 + wr * 32 + mt * 16 + g;
        int r1 = r0 + 8;
        float d0 = (r0 < NN) ? g_dis[r0] : 0.0f;
        float d1 = (r1 < NN) ? g_dis[r1] : 0.0f;
#pragma unroll
        for (int nt = 0; nt < 4; nt++) {
            int colh = wc * 16 + nt * 4 + tig;   // fp16x2 index
            if (r0 < NN)
                g_hsb[r0 * 64 + colh] = __floats2half2_rn(c[mt][nt][0] * d0,
                                                          c[mt][nt][1] * d0);
            if (r1 < NN)
                g_hsb[r1 * 64 + colh] = __floats2half2_rn(c[mt][nt][2] * d1,
                                                          c[mt][nt][3] * d1);
        }
    }
}

// ---------------- CSR pull aggregation: warp per node ----------------------
__global__ void k_aggregate(const float* __restrict__ bias) {
    int t = blockIdx.x * blockDim.x + threadIdx.x;
    if (blockIdx.x == 0 && threadIdx.x < 128) {
        g_sum[threadIdx.x] = 0.0f;
        g_sumsq[threadIdx.x] = 0.0f;
    }
    int n = t >> 5, q = t & 31;
    if (n >= NN) return;
    int beg = g_rowptr[n], end = g_rowptr[n + 1];

    uint2 u = *(const uint2*)(g_hsb + n * 64 + q * 2);   // self term
    float2 p0 = __half22float2(*reinterpret_cast<__half2*>(&u.x));
    float2 p1 = __half22float2(*reinterpret_cast<__half2*>(&u.y));
    float a0 = p0.x, a1 = p0.y, a2 = p1.x, a3 = p1.y;

    for (int i = beg; i < end; i++) {
        int s = g_csrsrc[i];                              // warp-uniform broadcast
        uint2 v = *(const uint2*)(g_hsb + s * 64 + q * 2);
        float2 q0 = __half22float2(*reinterpret_cast<__half2*>(&v.x));
        float2 q1 = __half22float2(*reinterpret_cast<__half2*>(&v.y));
        a0 += q0.x; a1 += q0.y; a2 += q1.x; a3 += q1.y;
    }
    float d = g_dis[n];
    float4 b = ((const float4*)bias)[q];
    float4 acc;
    acc.x = a0 * d + b.x;
    acc.y = a1 * d + b.y;
    acc.z = a2 * d + b.z;
    acc.w = a3 * d + b.w;
    ((float4*)g_agg)[n * 32 + q] = acc;
}

// ---------------- BN stats (streaming); also zeroes pool buffers ----------
__global__ void k_bnstats() {
    int c = threadIdx.x;
    int zt = blockIdx.x * blockDim.x + c;
    if (zt < GG * HH) g_pool[zt] = 0.0f;
    if (zt < GG) g_cnt[zt] = 0.0f;

    float s = 0.0f, ss = 0.0f;
    for (int n = blockIdx.x; n < NN; n += gridDim.x) {
        float v = g_agg[n * HH + c];
        s += v;
        ss += v * v;
    }
    atomicAdd(&g_sum[c], s);
    atomicAdd(&g_sumsq[c], ss);
}

// ---------------- pooling (BN apply + relu from raw stats) ----------------
__global__ void k_pool(const int* __restrict__ batch,
                       const float* __restrict__ gamma,
                       const float* __restrict__ beta) {
    int t = blockIdx.x * blockDim.x + threadIdx.x;
    int n = t >> 5, q = t & 31;
    if (n >= NN) return;
    int g = batch[n];
    const float invN = 1.0f / (float)NN;
    float4 v = ((const float4*)g_agg)[n * 32 + q];
    float4 sm = ((const float4*)g_sum)[q];
    float4 sq = ((const float4*)g_sumsq)[q];
    float4 ga = ((const float4*)gamma)[q];
    float4 be = ((const float4*)beta)[q];
    float4 o;
    {
        float mu = sm.x * invN; float var = sq.x * invN - mu * mu;
        float sc = ga.x * rsqrtf(var + EPS);
        o.x = fmaxf(v.x * sc + (be.x - mu * sc), 0.f);
    }
    {
        float mu = sm.y * invN; float var = sq.y * invN - mu * mu;
        float sc = ga.y * rsqrtf(var + EPS);
        o.y = fmaxf(v.y * sc + (be.y - mu * sc), 0.f);
    }
    {
        float mu = sm.z * invN; float var = sq.z * invN - mu * mu;
        float sc = ga.z * rsqrtf(var + EPS);
        o.z = fmaxf(v.z * sc + (be.z - mu * sc), 0.f);
    }
    {
        float mu = sm.w * invN; float var = sq.w * invN - mu * mu;
        float sc = ga.w * rsqrtf(var + EPS);
        o.w = fmaxf(v.w * sc + (be.w - mu * sc), 0.f);
    }
    float* out = g_pool + (size_t)g * HH + q * 4;
    asm volatile("red.global.add.v4.f32 [%0], {%1,%2,%3,%4};"
                 :: "l"(out), "f"(o.x), "f"(o.y), "f"(o.z), "f"(o.w)
                 : "memory");
    if (q == 0) atomicAdd(&g_cnt[g], 1.0f);
}

// ---------------- MLP head (+ re-arm g_degi / g_scancnt) ------------------
__global__ void k_mlp(const float* __restrict__ w1, const float* __restrict__ b1,
                      const float* __restrict__ w2, const float* __restrict__ b2,
                      float* __restrict__ out) {
    int g = blockIdx.x;
    int t = threadIdx.x;       // 128

    int zi = g * 128 + t;
    if (zi < NN) g_degi[zi] = 0;
    if (zi == 0) g_scancnt = 0;

    __shared__ float p[128];
    __shared__ float red[4][8];
    float inv = 1.0f / fmaxf(g_cnt[g], 1.0f);
    p[t] = g_pool[g * HH + t] * inv;
    __syncthreads();
    float acc = b1[t];
#pragma unroll 8
    for (int k = 0; k < 128; k++) acc += p[k] * w1[k * 128 + t];
    float h = fmaxf(acc, 0.0f);
    float pr[CC];
#pragma unroll
    for (int c = 0; c < CC; c++) pr[c] = h * w2[t * CC + c];
#pragma unroll
    for (int off = 16; off > 0; off >>= 1)
#pragma unroll
        for (int c = 0; c < CC; c++) pr[c] += __shfl_down_sync(0xffffffffu, pr[c], off);
    int w = t >> 5, lane = t & 31;
    if (lane == 0)
#pragma unroll
        for (int c = 0; c < CC; c++) red[w][c] = pr[c];
    __syncthreads();
    if (t < CC) {
        out[g * CC + t] = red[0][t] + red[1][t] + red[2][t] + red[3][t] + b2[t];
    }
}

// ---------------- launch ----------------
extern "C" void kernel_launch(void* const* d_in, const int* in_sizes, int n_in,
                              void* d_out, int out_size) {
    const float* x      = (const float*)d_in[0];
    const int*   ei     = (const int*)d_in[1];
    const int*   batch  = (const int*)d_in[2];
    const float* conv_w = (const float*)d_in[3];
    const float* conv_b = (const float*)d_in[4];
    const float* bn_g   = (const float*)d_in[5];
    const float* bn_b   = (const float*)d_in[6];
    const float* w1     = (const float*)d_in[7];
    const float* b1     = (const float*)d_in[8];
    const float* w2     = (const float*)d_in[9];
    const float* b2     = (const float*)d_in[10];
    float* out = (float*)d_out;

    const int* src = ei;
    const int* dst = ei + EE;

    k_deg_count<<<(EE / 4 + 255) / 256, 256>>>(dst);
    k_csr_mid<<<NBLK, 256>>>();
    k_fill<<<(EE / 4 + 255) / 256, 256>>>(src, dst);

    const int ggrid = (NN + 63) / 64;      // 782
    const int nwarp_blocks = (int)(((long long)NN * 32 + 255) / 256);

    for (int l = 0; l < LL; l++) {
        const float* A = (l == 0) ? x : nullptr;   // nullptr -> g_agg with BN prologue
        const float* ga = (l > 0) ? bn_g + (size_t)(l - 1) * HH : nullptr;
        const float* be = (l > 0) ? bn_b + (size_t)(l - 1) * HH : nullptr;
        k_gemm<<<ggrid, 256>>>(A, conv_w + (size_t)l * HH * HH, ga, be, l > 0 ? 1 : 0);
        k_aggregate<<<nwarp_blocks, 256>>>(conv_b + (size_t)l * HH);
        k_bnstats<<<1024, 128>>>();
    }

    k_pool<<<nwarp_blocks, 256>>>(batch, bn_g + (size_t)(LL - 1) * HH,
                                  bn_b + (size_t)(LL - 1) * HH);
    k_mlp<<<GG, 128>>>(w1, b1, w2, b2, out);
}